// round 15
// baseline (speedup 1.0000x reference)
#include <cuda_runtime.h>
#include <cuda_bf16.h>
#include <math.h>
#include <stdint.h>

#define BATCH 8
#define TT 96
#define NNODE 200
#define EMB 32
#define HID 32
#define HOR 24
#define FV 400
#define KEV 200
#define KP 208               /* KEV padded to 16 */
#define NSEQ (BATCH*NNODE)   /* 1600 */
#define ROWS (BATCH*TT)      /* 768  */
#define HMT 6400

// ---- scratch (static device globals; no allocations allowed) ----
__device__ float g_E[ROWS*TT];
__device__ __nv_bfloat16 g_attH[ROWS*KP];   // attention hi split
__device__ __nv_bfloat16 g_attL[ROWS*KP];   // attention lo split
__device__ __nv_bfloat16 g_vweH[HMT*KP];    // even v_w cols hi split (2.7MB)
__device__ __nv_bfloat16 g_vweL[HMT*KP];    // lo split
__device__ int   g_zf[BATCH*NNODE];         // per-(b,n) all-masked flag
__device__ float g_colsum[HMT];             // vb + sum of odd v_w columns
__device__ float g_Y[ROWS*HMT];             // mtan output, 19.6 MB
__device__ float g_GI[NSEQ*TT*96];          // gi gates, [seq][t][96], 59 MB

__device__ __forceinline__ float sigf(float x){ return 1.0f/(1.0f + __expf(-x)); }
__device__ __forceinline__ float ftanh(float x){ return 2.0f*sigf(2.0f*x) - 1.0f; }

__device__ __forceinline__ void mma_bf16(float& d0,float& d1,float& d2,float& d3,
    uint32_t a0,uint32_t a1,uint32_t a2,uint32_t a3, uint32_t b0,uint32_t b1){
    asm volatile("mma.sync.aligned.m16n8k16.row.col.f32.bf16.bf16.f32 "
        "{%0,%1,%2,%3}, {%4,%5,%6,%7}, {%8,%9}, {%0,%1,%2,%3};\n"
        : "+f"(d0),"+f"(d1),"+f"(d2),"+f"(d3)
        : "r"(a0),"r"(a1),"r"(a2),"r"(a3), "r"(b0),"r"(b1));
}

#define CP_ASYNC16(dst, src) \
    asm volatile("cp.async.cg.shared.global [%0], [%1], 16;\n" \
        :: "r"(dst), "l"(src))
#define CP_COMMIT() asm volatile("cp.async.commit_group;\n")
#define CP_WAIT(n)  asm volatile("cp.async.wait_group %0;\n" :: "n"(n))

// packed f32x2 helpers (B200 FFMA2 — PTX-only)
__device__ __forceinline__ uint64_t pk2(float lo, float hi){
    uint64_t r; asm("mov.b64 %0, {%1,%2};" : "=l"(r) : "f"(lo), "f"(hi)); return r;
}
__device__ __forceinline__ void upk2(float& lo, float& hi, uint64_t v){
    asm("mov.b64 {%0,%1}, %2;" : "=f"(lo), "=f"(hi) : "l"(v));
}
__device__ __forceinline__ void ffma2(uint64_t& d, uint64_t a, uint64_t b, uint64_t c){
    asm("fma.rn.f32x2 %0, %1, %2, %3;" : "=l"(d) : "l"(a), "l"(b), "l"(c));
}

// ---------------------------------------------------------------------------
// KQK: fused time-embedding + q/k projection + scores + row-max + E.
// grid=(3, 8), 192 threads.
// ---------------------------------------------------------------------------
__global__ void __launch_bounds__(192)
kQK(const float* __restrict__ ts, const float* __restrict__ te_w,
    const float* __restrict__ te_b, const float* __restrict__ q_w,
    const float* __restrict__ q_b, const float* __restrict__ k_w){
    int b = blockIdx.y, q0 = blockIdx.x*32;
    int tid = threadIdx.x;
    __shared__ float te_s[TT][33];
    __shared__ float ks_s[TT][33];
    __shared__ float qs[32][33];
    __shared__ float sc[32][97];

    for (int idx = tid; idx < TT*EMB; idx += 192){
        int row = idx >> 5, e = idx & 31;
        float v = ts[b*TT+row]*te_w[e] + te_b[e];
        if (e > 0) v = sinf(v);
        te_s[row][e] = v;
    }
    __syncthreads();
    for (int idx = tid; idx < TT*EMB; idx += 192){
        int row = idx >> 5, e = idx & 31;
        float k = 0.f;
        #pragma unroll
        for (int i=0;i<EMB;i++) k = fmaf(te_s[row][i], k_w[e*EMB+i], k);
        ks_s[row][e] = k;
    }
    for (int idx = tid; idx < 32*EMB; idx += 192){
        int row = idx >> 5, e = idx & 31;
        float q = q_b[e];
        #pragma unroll
        for (int i=0;i<EMB;i++) q = fmaf(te_s[q0+row][i], q_w[e*EMB+i], q);
        qs[row][e] = q;
    }
    __syncthreads();
    for (int idx = tid; idx < 32*TT; idx += 192){
        int qq = idx / TT, kk = idx - qq*TT;
        float s = 0.f;
        #pragma unroll
        for (int i=0;i<EMB;i++) s = fmaf(qs[qq][i], ks_s[kk][i], s);
        sc[qq][kk] = s * 0.17677669529663687f;
    }
    __syncthreads();
    int w = tid>>5, lane = tid&31;
    for (int r = w; r < 32; r += 6){
        float s0 = sc[r][lane], s1 = sc[r][lane+32], s2 = sc[r][lane+64];
        float m = fmaxf(s0, fmaxf(s1, s2));
        #pragma unroll
        for (int o=16;o;o>>=1) m = fmaxf(m, __shfl_xor_sync(0xffffffffu, m, o));
        float* er = g_E + ((size_t)b*TT + q0 + r)*TT;
        er[lane]    = __expf(s0 - m);
        er[lane+32] = __expf(s1 - m);
        er[lane+64] = __expf(s2 - m);
    }
}

// ---------------------------------------------------------------------------
// K2: masked softmax aggregation, query-split. grid=(25, 8, 3).
// ---------------------------------------------------------------------------
__global__ void __launch_bounds__(256)
k2_att(const float* __restrict__ x, const float* __restrict__ mask){
    int b = blockIdx.y, n0 = blockIdx.x*8, q0 = blockIdx.z*32;
    int tid = threadIdx.x, w = tid>>5, lane = tid&31;
    int n = n0 + w;
    __shared__ float Es[32][97];
    __shared__ float xs[TT][9];
    __shared__ float ms[TT][9];
    __shared__ float ssx[8];
    const float* xb = x    + (size_t)b*TT*NNODE + n0;
    const float* mb = mask + (size_t)b*TT*NNODE + n0;
    for (int idx = tid; idx < TT*8; idx += 256){
        int t = idx>>3, i = idx&7;
        xs[t][i] = xb[t*NNODE + i];
        ms[t][i] = mb[t*NNODE + i];
    }
    for (int q=w; q<32; q+=8){
        const float* er = g_E + ((size_t)b*TT + q0 + q)*TT;
        Es[q][lane]    = er[lane];
        Es[q][lane+32] = er[lane+32];
        Es[q][lane+64] = er[lane+64];
    }
    __syncthreads();
    float sx = 0.f;
    #pragma unroll
    for (int t=lane; t<TT; t+=32) sx += xs[t][w];
    #pragma unroll
    for (int o=16;o;o>>=1) sx += __shfl_xor_sync(0xffffffffu, sx, o);
    if (lane==0) ssx[w] = sx;
    __syncwarp();

    float num=0.f, den=0.f;
    #pragma unroll 4
    for (int k=0;k<TT;k++){
        float mm = ms[k][w];
        float mx = mm * xs[k][w];
        float e  = Es[lane][k];
        den += e*mm;
        num  = fmaf(e, mx, num);
    }
    bool nz = (den > 0.f);
    float v = nz ? num/den : ssx[w]*(1.0f/96.0f);
    __nv_bfloat16 hi = __float2bfloat16(v);
    __nv_bfloat16 lo = __float2bfloat16(v - __bfloat162float(hi));
    size_t row = (size_t)b*TT + q0 + lane;
    g_attH[row*KP + n] = hi;
    g_attL[row*KP + n] = lo;
    if (lane==0 && blockIdx.z==0) g_zf[b*NNODE + n] = nz ? 0 : 1;
}

// ---------------------------------------------------------------------------
// K2b: pack even v_w columns as bf16 hi/lo splits; colsum = vb + sum(odd).
// ---------------------------------------------------------------------------
__global__ void k2b_pack(const float* __restrict__ vw, const float* __restrict__ vb){
    int j = (blockIdx.x*256 + threadIdx.x) >> 5;
    int lane = threadIdx.x & 31;
    const float4* src = (const float4*)(vw + (size_t)j*FV);
    float os = 0.f;
    #pragma unroll
    for (int c=lane; c<100; c+=32){
        float4 v = src[c];
        __nv_bfloat16 h0 = __float2bfloat16(v.x);
        __nv_bfloat16 h1 = __float2bfloat16(v.z);
        g_vweH[(size_t)j*KP + 2*c]   = h0;
        g_vweH[(size_t)j*KP + 2*c+1] = h1;
        g_vweL[(size_t)j*KP + 2*c]   = __float2bfloat16(v.x - __bfloat162float(h0));
        g_vweL[(size_t)j*KP + 2*c+1] = __float2bfloat16(v.z - __bfloat162float(h1));
        os += v.y + v.w;
    }
    if (lane < 8){
        g_vweH[(size_t)j*KP + 200 + lane] = __float2bfloat16(0.f);
        g_vweL[(size_t)j*KP + 200 + lane] = __float2bfloat16(0.f);
    }
    if (j < ROWS){
        if (lane < 8)       g_attH[(size_t)j*KP + 200 + lane] = __float2bfloat16(0.f);
        else if (lane < 16) g_attL[(size_t)j*KP + 200 + (lane-8)] = __float2bfloat16(0.f);
    }
    #pragma unroll
    for (int o=16;o;o>>=1) os += __shfl_xor_sync(0xffffffffu, os, o);
    if (lane == 0) g_colsum[j] = vb[j] + os;
}

// ---------------------------------------------------------------------------
// K3: Y[768x6400] = att[768x208] @ vwe[6400x208]^T + colsum
// bf16 3-term split GEMM. cp.async 3-STAGE ring, depth-2 prefetch,
// ONE barrier per k-chunk. 128x128 tile, BK=16 (13 chunks), 2 CTAs/SM.
// ---------------------------------------------------------------------------
#define K3_STAGE_B 24576              /* 4 arrays x 1536 u32 x 4B */
#define K3_SMEM (3*K3_STAGE_B + 512)
__global__ void __launch_bounds__(256,2)
k3_vgemm_bf(){
    extern __shared__ uint32_t dsm[];
    float* csh = (float*)(dsm + 3*6144);

    int tid = threadIdx.x;
    int bn = blockIdx.x, bm = blockIdx.y;
    int warp = tid>>5, lane = tid&31;
    int wm = warp>>2, wn = warp&3;          // 2 x 4 warp grid
    int g = lane>>2, c = lane&3;

    int lrow = tid>>1;                      // 0..127
    int half = tid&1;                       // 16B quad within 32B k-chunk row

    const uint4* AgH = (const uint4*)(g_attH + (size_t)(bm*128 + lrow)*KP);
    const uint4* AgL = (const uint4*)(g_attL + (size_t)(bm*128 + lrow)*KP);
    const uint4* BgH = (const uint4*)(g_vweH + (size_t)(bn*128 + lrow)*KP);
    const uint4* BgL = (const uint4*)(g_vweL + (size_t)(bn*128 + lrow)*KP);

    if (tid < 128) csh[tid] = g_colsum[bn*128 + tid];

    // per-thread cp.async destinations: byte offset within an array
    uint32_t off = (lrow*12 + half*4)*4;
    uint32_t sbase = (uint32_t)__cvta_generic_to_shared(dsm);
    // array byte offsets within a stage: AsH +0, AsL +6144, BsH +12288, BsL +18432

    // prologue: chunks 0,1 into stages 0,1
    #pragma unroll
    for (int p=0; p<2; p++){
        uint32_t sb = sbase + p*K3_STAGE_B + off;
        CP_ASYNC16(sb        , AgH + p*2 + half);
        CP_ASYNC16(sb + 6144 , AgL + p*2 + half);
        CP_ASYNC16(sb + 12288, BgH + p*2 + half);
        CP_ASYNC16(sb + 18432, BgL + p*2 + half);
        CP_COMMIT();
    }

    float acc[4][4][4];
    #pragma unroll
    for (int i=0;i<4;i++)
        #pragma unroll
        for (int j=0;j<4;j++)
            #pragma unroll
            for (int r=0;r<4;r++) acc[i][j][r]=0.f;

    int cs = 0;          // stage being consumed
    int ws = 2;          // stage to fill next
    #pragma unroll 1
    for (int it=0; it<13; ++it){
        if (it < 11) { CP_WAIT(1); } else { CP_WAIT(0); }
        __syncthreads();                        // stage cs ready; prior reads of ws done
        if (it < 11){
            uint32_t sb = sbase + ws*K3_STAGE_B + off;
            CP_ASYNC16(sb        , AgH + (it+2)*2 + half);
            CP_ASYNC16(sb + 6144 , AgL + (it+2)*2 + half);
            CP_ASYNC16(sb + 12288, BgH + (it+2)*2 + half);
            CP_ASYNC16(sb + 18432, BgL + (it+2)*2 + half);
            CP_COMMIT();
        }

        const uint32_t* AsH = dsm + cs*6144;
        const uint32_t* AsL = AsH + 1536;
        const uint32_t* BsH = AsH + 3072;
        const uint32_t* BsL = AsH + 4608;

        uint32_t aH[4][4], aL[4][4], bH[4][2], bL[4][2];
        #pragma unroll
        for (int mt=0; mt<4; mt++){
            int rb = wm*64 + mt*16 + g;
            aH[mt][0]=AsH[rb*12+c];       aH[mt][1]=AsH[(rb+8)*12+c];
            aH[mt][2]=AsH[rb*12+c+4];     aH[mt][3]=AsH[(rb+8)*12+c+4];
            aL[mt][0]=AsL[rb*12+c];       aL[mt][1]=AsL[(rb+8)*12+c];
            aL[mt][2]=AsL[rb*12+c+4];     aL[mt][3]=AsL[(rb+8)*12+c+4];
        }
        #pragma unroll
        for (int nt=0; nt<4; nt++){
            int nb = wn*32 + nt*8 + g;
            bH[nt][0]=BsH[nb*12+c]; bH[nt][1]=BsH[nb*12+c+4];
            bL[nt][0]=BsL[nb*12+c]; bL[nt][1]=BsL[nb*12+c+4];
        }
        #pragma unroll
        for (int mt=0; mt<4; mt++)
            #pragma unroll
            for (int nt=0; nt<4; nt++){
                float* d = acc[mt][nt];
                mma_bf16(d[0],d[1],d[2],d[3],
                         aH[mt][0],aH[mt][1],aH[mt][2],aH[mt][3],
                         bL[nt][0],bL[nt][1]);
                mma_bf16(d[0],d[1],d[2],d[3],
                         aL[mt][0],aL[mt][1],aL[mt][2],aL[mt][3],
                         bH[nt][0],bH[nt][1]);
                mma_bf16(d[0],d[1],d[2],d[3],
                         aH[mt][0],aH[mt][1],aH[mt][2],aH[mt][3],
                         bH[nt][0],bH[nt][1]);
            }
        cs = (cs==2)?0:cs+1;
        ws = (ws==2)?0:ws+1;
    }

    #pragma unroll
    for (int mt=0; mt<4; mt++){
        #pragma unroll
        for (int nt=0; nt<4; nt++){
            int colL = wn*32 + nt*8 + 2*c;
            int col  = bn*128 + colL;
            float cs0 = csh[colL], cs1 = csh[colL+1];
            int r0 = bm*128 + wm*64 + mt*16 + g;
            float* d = acc[mt][nt];
            *(float2*)(g_Y + (size_t)r0*HMT + col) =
                make_float2(d[0]+cs0, d[1]+cs1);
            *(float2*)(g_Y + (size_t)(r0+8)*HMT + col) =
                make_float2(d[2]+cs0, d[3]+cs1);
        }
    }
}

// ---------------------------------------------------------------------------
// KGI: input-gate projection. block = one seq, 8 warps x 12-step chunks.
// (r,z) gates packed -> fma.rn.f32x2 halves FMA-pipe pressure.
// ---------------------------------------------------------------------------
#define TCH 12
__global__ void __launch_bounds__(256)
kGI(const float* __restrict__ wih, const float* __restrict__ bih,
    const float* __restrict__ vw){
    __shared__ float wsh[96][33];       // 12.4 KB, padded
    int tid = threadIdx.x;
    for (int idx = tid; idx < 96*32; idx += 256)
        wsh[idx>>5][idx&31] = wih[idx];
    __syncthreads();

    int w = tid>>5, j = tid&31;
    int seq = blockIdx.x;
    int t0  = w * TCH;
    int b = seq / NNODE, n = seq % NNODE;

    uint64_t wrz[32]; float wn_[32];
    #pragma unroll
    for (int i=0;i<32;i++){
        wrz[i] = pk2(wsh[j][i], wsh[32+j][i]);
        wn_[i] = wsh[64+j][i];
    }

    // all-masked-node correction (exact; probability ~2^-96 per node)
    float c0=0.f, c1=0.f, c2=0.f;
    {
        int anyz = 0;
        for (int i=j; i<NNODE; i+=32) anyz |= g_zf[b*NNODE+i];
        anyz = __reduce_or_sync(0xffffffffu, anyz);
        if (anyz){
            for (int n0=0;n0<NNODE;n0++){
                if (g_zf[b*NNODE+n0]){
                    #pragma unroll
                    for (int i=0;i<32;i++){
                        float vv = vw[((size_t)n*32+i)*FV + 2*n0 + 1];
                        float wr_i, wz_i; upk2(wr_i, wz_i, wrz[i]);
                        c0 = fmaf(wr_i,  vv, c0);
                        c1 = fmaf(wz_i,  vv, c1);
                        c2 = fmaf(wn_[i],vv, c2);
                    }
                }
            }
        }
    }
    uint64_t brz = pk2(bih[j] - c0, bih[32+j] - c1);
    float bnn = bih[64+j] - c2;

    const float* xb = g_Y + (size_t)b*TT*HMT + n*HID + j + (size_t)t0*HMT;
    float* gp = g_GI + (size_t)seq*TT*96 + t0*96;

    float xq[2];
    xq[0] = xb[0];
    xq[1] = xb[HMT];

    #pragma unroll
    for (int t=0;t<TCH;t++){
        float xc = xq[t&1];
        if (t+2 < TCH) xq[t&1] = xb[(size_t)(t+2)*HMT];
        uint64_t grz = brz;
        float gn = bnn;
        #pragma unroll
        for (int i=0;i<32;i++){
            float xv = __shfl_sync(0xffffffffu, xc, i);
            uint64_t xv2 = pk2(xv, xv);
            ffma2(grz, wrz[i], xv2, grz);
            gn = fmaf(wn_[i], xv, gn);
        }
        float gr, gz; upk2(gr, gz, grz);
        gp[t*96 +      j] = gr;
        gp[t*96 + 32 + j] = gz;
        gp[t*96 + 64 + j] = gn;
    }
}

// ---------------------------------------------------------------------------
// K5: lean GRU recurrence + fused MLP decoder. (r,z) packed via fma.rn.f32x2.
// ---------------------------------------------------------------------------
__global__ void __launch_bounds__(128)
k5_gru(const float* __restrict__ whh, const float* __restrict__ bhh,
       const float* __restrict__ mlp_w, const float* __restrict__ mlp_b,
       const float* __restrict__ out_w, const float* __restrict__ out_b,
       float* __restrict__ out){
    __shared__ float ush[96][33];       // 12.4 KB, padded
    int tid = threadIdx.x;
    for (int idx = tid; idx < 96*32; idx += 128)
        ush[idx>>5][idx&31] = whh[idx];
    __syncthreads();

    int wid = tid >> 5;
    int j   = tid & 31;
    int seq = blockIdx.x*4 + wid;
    int b = seq / NNODE, n = seq % NNODE;

    uint64_t urz[32]; float un_[32];
    #pragma unroll
    for (int i=0;i<32;i++){
        urz[i] = pk2(ush[j][i], ush[32+j][i]);
        un_[i] = ush[64+j][i];
    }
    uint64_t brz = pk2(bhh[j], bhh[32+j]);
    float bhn = bhh[64+j];

    const float* gp = g_GI + (size_t)seq*TT*96;
    float a0 = gp[j], a1 = gp[32+j], a2 = gp[64+j];

    float h = 0.f;
    #pragma unroll 2
    for (int t=0;t<TT;t++){
        const float* nx = gp + ((t<TT-1)? t+1 : t)*96;
        float p0 = nx[j], p1 = nx[32+j], p2 = nx[64+j];
        uint64_t hrz = brz;
        float hn = 0.f;
        #pragma unroll
        for (int i=0;i<32;i++){
            float hv = __shfl_sync(0xffffffffu, h, i);
            uint64_t hv2 = pk2(hv, hv);
            ffma2(hrz, urz[i], hv2, hrz);
            hn = fmaf(un_[i], hv, hn);
        }
        float hr, hz; upk2(hr, hz, hrz);
        float r  = sigf(a0 + hr);
        float z  = sigf(a1 + hz);
        float nn = ftanh(a2 + r*(hn + bhn));
        h = (1.f - z)*nn + z*h;
        a0 = p0; a1 = p1; a2 = p2;
    }

    float h2 = mlp_b[j];
    #pragma unroll
    for (int i=0;i<32;i++)
        h2 = fmaf(mlp_w[j*32+i], __shfl_sync(0xffffffffu, h, i), h2);
    h2 = fmaxf(h2, 0.f);

    float y = (j < HOR) ? out_b[j] : 0.f;
    #pragma unroll
    for (int i=0;i<32;i++){
        float v = __shfl_sync(0xffffffffu, h2, i);
        if (j < HOR) y = fmaf(out_w[j*32+i], v, y);
    }
    if (j < HOR) out[((size_t)b*HOR + j)*NNODE + n] = y;
}

// ---------------------------------------------------------------------------
extern "C" void kernel_launch(void* const* d_in, const int* in_sizes, int n_in,
                              void* d_out, int out_size){
    const float* x    = (const float*)d_in[0];
    const float* mask = (const float*)d_in[2];
    const float* ts   = (const float*)d_in[3];
    const float* te_w = (const float*)d_in[4];
    const float* te_b = (const float*)d_in[5];
    const float* q_w  = (const float*)d_in[6];
    const float* q_b  = (const float*)d_in[7];
    const float* k_w  = (const float*)d_in[8];
    const float* v_w  = (const float*)d_in[9];
    const float* v_b  = (const float*)d_in[10];
    const float* wih  = (const float*)d_in[11];
    const float* whh  = (const float*)d_in[12];
    const float* bih  = (const float*)d_in[13];
    const float* bhh  = (const float*)d_in[14];
    const float* mlpw = (const float*)d_in[15];
    const float* mlpb = (const float*)d_in[16];
    const float* outw = (const float*)d_in[17];
    const float* outb = (const float*)d_in[18];
    float* out = (float*)d_out;

    cudaFuncSetAttribute(k3_vgemm_bf,
        cudaFuncAttributeMaxDynamicSharedMemorySize, K3_SMEM);

    kQK<<<dim3(3, BATCH), 192>>>(ts, te_w, te_b, q_w, q_b, k_w);
    k2b_pack<<<800, 256>>>(v_w, v_b);
    k2_att<<<dim3(25, BATCH, 3), 256>>>(x, mask);
    k3_vgemm_bf<<<dim3(HMT/128, ROWS/128), 256, K3_SMEM>>>();
    kGI<<<NSEQ, 256>>>(wih, bih, v_w);
    k5_gru<<<NSEQ/4, 128>>>(whh, bhh, mlpw, mlpb, outw, outb, out);
}

// round 16
// speedup vs baseline: 1.0889x; 1.0889x over previous
#include <cuda_runtime.h>
#include <cuda_bf16.h>
#include <math.h>
#include <stdint.h>

#define BATCH 8
#define TT 96
#define NNODE 200
#define EMB 32
#define HID 32
#define HOR 24
#define FV 400
#define KEV 200
#define KP 208               /* KEV padded to 16 */
#define NSEQ (BATCH*NNODE)   /* 1600 */
#define ROWS (BATCH*TT)      /* 768  */
#define HMT 6400

// ---- scratch (static device globals; no allocations allowed) ----
__device__ float g_E[ROWS*TT];
__device__ __nv_bfloat16 g_attH[ROWS*KP];   // attention hi split
__device__ __nv_bfloat16 g_attL[ROWS*KP];   // attention lo split
__device__ __nv_bfloat16 g_vweH[HMT*KP];    // even v_w cols hi split (2.7MB)
__device__ __nv_bfloat16 g_vweL[HMT*KP];    // lo split
__device__ int   g_zf[BATCH*NNODE];         // per-(b,n) all-masked flag
__device__ float g_colsum[HMT];             // vb + sum of odd v_w columns
__device__ float g_Y[ROWS*HMT];             // mtan output, 19.6 MB
__device__ float g_GI[NSEQ*TT*96];          // gi gates, [seq][t][96], 59 MB

__device__ __forceinline__ float sigf(float x){ return 1.0f/(1.0f + __expf(-x)); }
__device__ __forceinline__ float ftanh(float x){ return 2.0f*sigf(2.0f*x) - 1.0f; }

__device__ __forceinline__ void mma_bf16(float& d0,float& d1,float& d2,float& d3,
    uint32_t a0,uint32_t a1,uint32_t a2,uint32_t a3, uint32_t b0,uint32_t b1){
    asm volatile("mma.sync.aligned.m16n8k16.row.col.f32.bf16.bf16.f32 "
        "{%0,%1,%2,%3}, {%4,%5,%6,%7}, {%8,%9}, {%0,%1,%2,%3};\n"
        : "+f"(d0),"+f"(d1),"+f"(d2),"+f"(d3)
        : "r"(a0),"r"(a1),"r"(a2),"r"(a3), "r"(b0),"r"(b1));
}

#define CP_ASYNC16(dst, src) \
    asm volatile("cp.async.cg.shared.global [%0], [%1], 16;\n" \
        :: "r"(dst), "l"(src))
#define CP_COMMIT() asm volatile("cp.async.commit_group;\n")
#define CP_WAIT(n)  asm volatile("cp.async.wait_group %0;\n" :: "n"(n))

// ---------------------------------------------------------------------------
// KQK: fused time-embedding + q/k projection + scores + row-max + E.
// grid=(3, 8), 192 threads.
// ---------------------------------------------------------------------------
__global__ void __launch_bounds__(192)
kQK(const float* __restrict__ ts, const float* __restrict__ te_w,
    const float* __restrict__ te_b, const float* __restrict__ q_w,
    const float* __restrict__ q_b, const float* __restrict__ k_w){
    int b = blockIdx.y, q0 = blockIdx.x*32;
    int tid = threadIdx.x;
    __shared__ float te_s[TT][33];
    __shared__ float ks_s[TT][33];
    __shared__ float qs[32][33];
    __shared__ float sc[32][97];

    for (int idx = tid; idx < TT*EMB; idx += 192){
        int row = idx >> 5, e = idx & 31;
        float v = ts[b*TT+row]*te_w[e] + te_b[e];
        if (e > 0) v = sinf(v);
        te_s[row][e] = v;
    }
    __syncthreads();
    for (int idx = tid; idx < TT*EMB; idx += 192){
        int row = idx >> 5, e = idx & 31;
        float k = 0.f;
        #pragma unroll
        for (int i=0;i<EMB;i++) k = fmaf(te_s[row][i], k_w[e*EMB+i], k);
        ks_s[row][e] = k;
    }
    for (int idx = tid; idx < 32*EMB; idx += 192){
        int row = idx >> 5, e = idx & 31;
        float q = q_b[e];
        #pragma unroll
        for (int i=0;i<EMB;i++) q = fmaf(te_s[q0+row][i], q_w[e*EMB+i], q);
        qs[row][e] = q;
    }
    __syncthreads();
    for (int idx = tid; idx < 32*TT; idx += 192){
        int qq = idx / TT, kk = idx - qq*TT;
        float s = 0.f;
        #pragma unroll
        for (int i=0;i<EMB;i++) s = fmaf(qs[qq][i], ks_s[kk][i], s);
        sc[qq][kk] = s * 0.17677669529663687f;
    }
    __syncthreads();
    int w = tid>>5, lane = tid&31;
    for (int r = w; r < 32; r += 6){
        float s0 = sc[r][lane], s1 = sc[r][lane+32], s2 = sc[r][lane+64];
        float m = fmaxf(s0, fmaxf(s1, s2));
        #pragma unroll
        for (int o=16;o;o>>=1) m = fmaxf(m, __shfl_xor_sync(0xffffffffu, m, o));
        float* er = g_E + ((size_t)b*TT + q0 + r)*TT;
        er[lane]    = __expf(s0 - m);
        er[lane+32] = __expf(s1 - m);
        er[lane+64] = __expf(s2 - m);
    }
}

// ---------------------------------------------------------------------------
// K2: masked softmax aggregation, query-split. grid=(25, 8, 3).
// ---------------------------------------------------------------------------
__global__ void __launch_bounds__(256)
k2_att(const float* __restrict__ x, const float* __restrict__ mask){
    int b = blockIdx.y, n0 = blockIdx.x*8, q0 = blockIdx.z*32;
    int tid = threadIdx.x, w = tid>>5, lane = tid&31;
    int n = n0 + w;
    __shared__ float Es[32][97];
    __shared__ float xs[TT][9];
    __shared__ float ms[TT][9];
    __shared__ float ssx[8];
    const float* xb = x    + (size_t)b*TT*NNODE + n0;
    const float* mb = mask + (size_t)b*TT*NNODE + n0;
    for (int idx = tid; idx < TT*8; idx += 256){
        int t = idx>>3, i = idx&7;
        xs[t][i] = xb[t*NNODE + i];
        ms[t][i] = mb[t*NNODE + i];
    }
    for (int q=w; q<32; q+=8){
        const float* er = g_E + ((size_t)b*TT + q0 + q)*TT;
        Es[q][lane]    = er[lane];
        Es[q][lane+32] = er[lane+32];
        Es[q][lane+64] = er[lane+64];
    }
    __syncthreads();
    float sx = 0.f;
    #pragma unroll
    for (int t=lane; t<TT; t+=32) sx += xs[t][w];
    #pragma unroll
    for (int o=16;o;o>>=1) sx += __shfl_xor_sync(0xffffffffu, sx, o);
    if (lane==0) ssx[w] = sx;
    __syncwarp();

    float num=0.f, den=0.f;
    #pragma unroll 4
    for (int k=0;k<TT;k++){
        float mm = ms[k][w];
        float mx = mm * xs[k][w];
        float e  = Es[lane][k];
        den += e*mm;
        num  = fmaf(e, mx, num);
    }
    bool nz = (den > 0.f);
    float v = nz ? num/den : ssx[w]*(1.0f/96.0f);
    __nv_bfloat16 hi = __float2bfloat16(v);
    __nv_bfloat16 lo = __float2bfloat16(v - __bfloat162float(hi));
    size_t row = (size_t)b*TT + q0 + lane;
    g_attH[row*KP + n] = hi;
    g_attL[row*KP + n] = lo;
    if (lane==0 && blockIdx.z==0) g_zf[b*NNODE + n] = nz ? 0 : 1;
}

// ---------------------------------------------------------------------------
// K2b: pack even v_w columns as bf16 hi/lo splits; colsum = vb + sum(odd).
// ---------------------------------------------------------------------------
__global__ void k2b_pack(const float* __restrict__ vw, const float* __restrict__ vb){
    int j = (blockIdx.x*256 + threadIdx.x) >> 5;
    int lane = threadIdx.x & 31;
    const float4* src = (const float4*)(vw + (size_t)j*FV);
    float os = 0.f;
    #pragma unroll
    for (int c=lane; c<100; c+=32){
        float4 v = src[c];
        __nv_bfloat16 h0 = __float2bfloat16(v.x);
        __nv_bfloat16 h1 = __float2bfloat16(v.z);
        g_vweH[(size_t)j*KP + 2*c]   = h0;
        g_vweH[(size_t)j*KP + 2*c+1] = h1;
        g_vweL[(size_t)j*KP + 2*c]   = __float2bfloat16(v.x - __bfloat162float(h0));
        g_vweL[(size_t)j*KP + 2*c+1] = __float2bfloat16(v.z - __bfloat162float(h1));
        os += v.y + v.w;
    }
    if (lane < 8){
        g_vweH[(size_t)j*KP + 200 + lane] = __float2bfloat16(0.f);
        g_vweL[(size_t)j*KP + 200 + lane] = __float2bfloat16(0.f);
    }
    if (j < ROWS){
        if (lane < 8)       g_attH[(size_t)j*KP + 200 + lane] = __float2bfloat16(0.f);
        else if (lane < 16) g_attL[(size_t)j*KP + 200 + (lane-8)] = __float2bfloat16(0.f);
    }
    #pragma unroll
    for (int o=16;o;o>>=1) os += __shfl_xor_sync(0xffffffffu, os, o);
    if (lane == 0) g_colsum[j] = vb[j] + os;
}

// ---------------------------------------------------------------------------
// K3: Y[768x6400] = att[768x208] @ vwe[6400x208]^T + colsum
// bf16 3-term split GEMM, 128x160 tile, 320 threads (10 warps, 2x5 grid,
// warp tile 64x32). grid = 40x6 = 240 blocks -> SINGLE wave at 2 CTAs/SM.
// 2-stage cp.async ring.
// ---------------------------------------------------------------------------
#define K3_STAGE_B 27648   /* AsH 6144 + AsL 6144 + BsH 7680 + BsL 7680 bytes */
#define K3_SMEM (2*K3_STAGE_B + 1024)
__global__ void __launch_bounds__(320,2)
k3_vgemm_bf(){
    extern __shared__ uint32_t dsm[];
    float* csh = (float*)(dsm + 2*6912);

    int tid = threadIdx.x;
    int bn = blockIdx.x, bm = blockIdx.y;
    int warp = tid>>5, lane = tid&31;
    int wm = warp/5, wn = warp%5;           // 2 x 5 warp grid, tile 64x32
    int g = lane>>2, c = lane&3;

    int lrow = tid>>1;                      // A: 0..127 (tid<256); B: 0..159
    int half = tid&1;

    const uint4* AgH = (const uint4*)(g_attH + (size_t)(bm*128 + (lrow&127))*KP);
    const uint4* AgL = (const uint4*)(g_attL + (size_t)(bm*128 + (lrow&127))*KP);
    const uint4* BgH = (const uint4*)(g_vweH + (size_t)(bn*160 + lrow)*KP);
    const uint4* BgL = (const uint4*)(g_vweL + (size_t)(bn*160 + lrow)*KP);

    if (tid < 160) csh[tid] = g_colsum[bn*160 + tid];

    uint32_t offA = ((lrow&127)*12 + half*4)*4;
    uint32_t offB = (lrow*12 + half*4)*4;
    uint32_t sbase = (uint32_t)__cvta_generic_to_shared(dsm);
    // byte offsets within a stage: AsH +0, AsL +6144, BsH +12288, BsL +19968

    // prologue: chunk 0 -> stage 0
    if (tid < 256){
        CP_ASYNC16(sbase + offA,        AgH + half);
        CP_ASYNC16(sbase + 6144 + offA, AgL + half);
    }
    CP_ASYNC16(sbase + 12288 + offB, BgH + half);
    CP_ASYNC16(sbase + 19968 + offB, BgL + half);
    CP_COMMIT();

    float acc[4][4][4];
    #pragma unroll
    for (int i=0;i<4;i++)
        #pragma unroll
        for (int j=0;j<4;j++)
            #pragma unroll
            for (int r=0;r<4;r++) acc[i][j][r]=0.f;

    #pragma unroll 1
    for (int it=0; it<13; ++it){
        if (it < 12){
            uint32_t sb = sbase + ((it+1)&1)*K3_STAGE_B;
            if (tid < 256){
                CP_ASYNC16(sb + offA,        AgH + (it+1)*2 + half);
                CP_ASYNC16(sb + 6144 + offA, AgL + (it+1)*2 + half);
            }
            CP_ASYNC16(sb + 12288 + offB, BgH + (it+1)*2 + half);
            CP_ASYNC16(sb + 19968 + offB, BgL + (it+1)*2 + half);
            CP_COMMIT();
            CP_WAIT(1);
        } else {
            CP_WAIT(0);
        }
        __syncthreads();

        const uint32_t* AsH = dsm + (it&1)*6912;
        const uint32_t* AsL = AsH + 1536;
        const uint32_t* BsH = AsH + 3072;
        const uint32_t* BsL = AsH + 4992;

        uint32_t bH[4][2], bL[4][2];
        #pragma unroll
        for (int nt=0; nt<4; nt++){
            int nb = wn*32 + nt*8 + g;
            bH[nt][0]=BsH[nb*12+c]; bH[nt][1]=BsH[nb*12+c+4];
            bL[nt][0]=BsL[nb*12+c]; bL[nt][1]=BsL[nb*12+c+4];
        }
        #pragma unroll
        for (int mt=0; mt<4; mt++){
            int rb = wm*64 + mt*16 + g;
            uint32_t aH0=AsH[rb*12+c],   aH1=AsH[(rb+8)*12+c];
            uint32_t aH2=AsH[rb*12+c+4], aH3=AsH[(rb+8)*12+c+4];
            uint32_t aL0=AsL[rb*12+c],   aL1=AsL[(rb+8)*12+c];
            uint32_t aL2=AsL[rb*12+c+4], aL3=AsL[(rb+8)*12+c+4];
            #pragma unroll
            for (int nt=0; nt<4; nt++){
                float* d = acc[mt][nt];
                mma_bf16(d[0],d[1],d[2],d[3], aH0,aH1,aH2,aH3, bL[nt][0],bL[nt][1]);
                mma_bf16(d[0],d[1],d[2],d[3], aL0,aL1,aL2,aL3, bH[nt][0],bH[nt][1]);
                mma_bf16(d[0],d[1],d[2],d[3], aH0,aH1,aH2,aH3, bH[nt][0],bH[nt][1]);
            }
        }
        __syncthreads();
    }

    #pragma unroll
    for (int mt=0; mt<4; mt++){
        #pragma unroll
        for (int nt=0; nt<4; nt++){
            int colL = wn*32 + nt*8 + 2*c;
            int col  = bn*160 + colL;
            float cs0 = csh[colL], cs1 = csh[colL+1];
            int r0 = bm*128 + wm*64 + mt*16 + g;
            float* d = acc[mt][nt];
            *(float2*)(g_Y + (size_t)r0*HMT + col) =
                make_float2(d[0]+cs0, d[1]+cs1);
            *(float2*)(g_Y + (size_t)(r0+8)*HMT + col) =
                make_float2(d[2]+cs0, d[3]+cs1);
        }
    }
}

// ---------------------------------------------------------------------------
// KGI: input-gate projection. block = one seq, 8 warps x 12-step chunks.
// wih staged via padded smem (coalesced + conflict-free).  (R14 version)
// ---------------------------------------------------------------------------
#define TCH 12
__global__ void __launch_bounds__(256)
kGI(const float* __restrict__ wih, const float* __restrict__ bih,
    const float* __restrict__ vw){
    __shared__ float wsh[96][33];
    int tid = threadIdx.x;
    for (int idx = tid; idx < 96*32; idx += 256)
        wsh[idx>>5][idx&31] = wih[idx];
    __syncthreads();

    int w = tid>>5, j = tid&31;
    int seq = blockIdx.x;
    int t0  = w * TCH;
    int b = seq / NNODE, n = seq % NNODE;

    float wr[32], wz[32], wn[32];
    #pragma unroll
    for (int i=0;i<32;i++){
        wr[i] = wsh[j][i];
        wz[i] = wsh[32+j][i];
        wn[i] = wsh[64+j][i];
    }

    // all-masked-node correction (exact; probability ~2^-96 per node)
    float c0=0.f, c1=0.f, c2=0.f;
    {
        int anyz = 0;
        for (int i=j; i<NNODE; i+=32) anyz |= g_zf[b*NNODE+i];
        anyz = __reduce_or_sync(0xffffffffu, anyz);
        if (anyz){
            for (int n0=0;n0<NNODE;n0++){
                if (g_zf[b*NNODE+n0]){
                    #pragma unroll
                    for (int i=0;i<32;i++){
                        float vv = vw[((size_t)n*32+i)*FV + 2*n0 + 1];
                        c0 = fmaf(wr[i], vv, c0);
                        c1 = fmaf(wz[i], vv, c1);
                        c2 = fmaf(wn[i], vv, c2);
                    }
                }
            }
        }
    }
    float br  = bih[j]    - c0;
    float bz  = bih[32+j] - c1;
    float bnn = bih[64+j] - c2;

    const float* xb = g_Y + (size_t)b*TT*HMT + n*HID + j + (size_t)t0*HMT;
    float* gp = g_GI + (size_t)seq*TT*96 + t0*96;

    float xq[2];
    xq[0] = xb[0];
    xq[1] = xb[HMT];

    #pragma unroll
    for (int t=0;t<TCH;t++){
        float xc = xq[t&1];
        if (t+2 < TCH) xq[t&1] = xb[(size_t)(t+2)*HMT];
        float gr=br, gz=bz, gn=bnn;
        #pragma unroll
        for (int i=0;i<32;i++){
            float xv = __shfl_sync(0xffffffffu, xc, i);
            gr = fmaf(wr[i], xv, gr);
            gz = fmaf(wz[i], xv, gz);
            gn = fmaf(wn[i], xv, gn);
        }
        gp[t*96 +      j] = gr;
        gp[t*96 + 32 + j] = gz;
        gp[t*96 + 64 + j] = gn;
    }
}

// ---------------------------------------------------------------------------
// K5: lean GRU recurrence + fused MLP decoder. (R14 version)
// ---------------------------------------------------------------------------
__global__ void __launch_bounds__(128)
k5_gru(const float* __restrict__ whh, const float* __restrict__ bhh,
       const float* __restrict__ mlp_w, const float* __restrict__ mlp_b,
       const float* __restrict__ out_w, const float* __restrict__ out_b,
       float* __restrict__ out){
    __shared__ float ush[96][33];
    int tid = threadIdx.x;
    for (int idx = tid; idx < 96*32; idx += 128)
        ush[idx>>5][idx&31] = whh[idx];
    __syncthreads();

    int wid = tid >> 5;
    int j   = tid & 31;
    int seq = blockIdx.x*4 + wid;
    int b = seq / NNODE, n = seq % NNODE;

    float ur[32], uz[32], un[32];
    #pragma unroll
    for (int i=0;i<32;i++){
        ur[i] = ush[j][i];
        uz[i] = ush[32+j][i];
        un[i] = ush[64+j][i];
    }
    float bhr = bhh[j], bhz = bhh[32+j], bhn = bhh[64+j];

    const float* gp = g_GI + (size_t)seq*TT*96;
    float a0 = gp[j], a1 = gp[32+j], a2 = gp[64+j];

    float h = 0.f;
    #pragma unroll 2
    for (int t=0;t<TT;t++){
        const float* nx = gp + ((t<TT-1)? t+1 : t)*96;
        float p0 = nx[j], p1 = nx[32+j], p2 = nx[64+j];
        float hr=0.f, hz=0.f, hn=0.f;
        #pragma unroll
        for (int i=0;i<32;i++){
            float hv = __shfl_sync(0xffffffffu, h, i);
            hr = fmaf(ur[i], hv, hr);
            hz = fmaf(uz[i], hv, hz);
            hn = fmaf(un[i], hv, hn);
        }
        float r  = sigf(a0 + hr + bhr);
        float z  = sigf(a1 + hz + bhz);
        float nn = ftanh(a2 + r*(hn + bhn));
        h = (1.f - z)*nn + z*h;
        a0 = p0; a1 = p1; a2 = p2;
    }

    float h2 = mlp_b[j];
    #pragma unroll
    for (int i=0;i<32;i++)
        h2 = fmaf(mlp_w[j*32+i], __shfl_sync(0xffffffffu, h, i), h2);
    h2 = fmaxf(h2, 0.f);

    float y = (j < HOR) ? out_b[j] : 0.f;
    #pragma unroll
    for (int i=0;i<32;i++){
        float v = __shfl_sync(0xffffffffu, h2, i);
        if (j < HOR) y = fmaf(out_w[j*32+i], v, y);
    }
    if (j < HOR) out[((size_t)b*HOR + j)*NNODE + n] = y;
}

// ---------------------------------------------------------------------------
extern "C" void kernel_launch(void* const* d_in, const int* in_sizes, int n_in,
                              void* d_out, int out_size){
    const float* x    = (const float*)d_in[0];
    const float* mask = (const float*)d_in[2];
    const float* ts   = (const float*)d_in[3];
    const float* te_w = (const float*)d_in[4];
    const float* te_b = (const float*)d_in[5];
    const float* q_w  = (const float*)d_in[6];
    const float* q_b  = (const float*)d_in[7];
    const float* k_w  = (const float*)d_in[8];
    const float* v_w  = (const float*)d_in[9];
    const float* v_b  = (const float*)d_in[10];
    const float* wih  = (const float*)d_in[11];
    const float* whh  = (const float*)d_in[12];
    const float* bih  = (const float*)d_in[13];
    const float* bhh  = (const float*)d_in[14];
    const float* mlpw = (const float*)d_in[15];
    const float* mlpb = (const float*)d_in[16];
    const float* outw = (const float*)d_in[17];
    const float* outb = (const float*)d_in[18];
    float* out = (float*)d_out;

    cudaFuncSetAttribute(k3_vgemm_bf,
        cudaFuncAttributeMaxDynamicSharedMemorySize, K3_SMEM);

    kQK<<<dim3(3, BATCH), 192>>>(ts, te_w, te_b, q_w, q_b, k_w);
    k2b_pack<<<800, 256>>>(v_w, v_b);
    k2_att<<<dim3(25, BATCH, 3), 256>>>(x, mask);
    k3_vgemm_bf<<<dim3(HMT/160, ROWS/128), 320, K3_SMEM>>>();
    kGI<<<NSEQ, 256>>>(wih, bih, v_w);
    k5_gru<<<NSEQ/4, 128>>>(whh, bhh, mlpw, mlpb, outw, outb, out);
}